// round 2
// baseline (speedup 1.0000x reference)
#include <cuda_runtime.h>

// Problem shape (fixed by the reference): x, alpha: float32 [4, 8192, 1024]
// h_t = alpha_t * h_{t-1} + x_t   (inclusive scan along axis 1)

#define B_      4
#define S_      8192
#define D_      1024
#define R_      16                    // s-steps per thread (register-resident)
#define SUBS_   16                    // s-subchunks (warps) per block
#define TPB_    512                   // 32 d-lanes x 16 subchunks
#define DTILE_  32                    // d-lanes per block (= warp width)
#define SCHUNK_ (R_ * SUBS_)          // 256 s-steps per block/level
#define LEVELS_ (S_ / SCHUNK_)        // 32 levels per lane chain
#define LG_     (B_ * (D_ / DTILE_))  // 128 independent lane-group chains

// Inter-level handoff scratch (device globals: no allocation in kernel_launch).
__device__ float g_carry[LEVELS_][LG_][DTILE_];
__device__ int   g_flags[LEVELS_][LG_];

__global__ void zero_flags_kernel() {
    int i = blockIdx.x * blockDim.x + threadIdx.x;
    if (i < LEVELS_ * LG_) ((int*)g_flags)[i] = 0;
}

__global__ __launch_bounds__(TPB_, 2) void scan_kernel(const float* __restrict__ x,
                                                       const float* __restrict__ alpha,
                                                       float* __restrict__ out) {
    __shared__ float sp[SUBS_][DTILE_];   // per-subchunk cumprod(alpha)
    __shared__ float sl[SUBS_][DTILE_];   // per-subchunk local scan value
    __shared__ float s_cin[DTILE_];       // carry-in for this block (per d-lane)

    const int tid   = threadIdx.x;
    const int lane  = tid & 31;           // d within tile
    const int w     = tid >> 5;           // s-subchunk index (0..15)
    const int lg    = blockIdx.x;         // lane-group: b * 32 + dtile
    const int level = blockIdx.y;         // s-chunk level (chain position)
    const int b     = lg >> 5;
    const int dt    = lg & 31;
    const int d     = dt * DTILE_ + lane;
    const int s0    = level * SCHUNK_ + w * R_;
    const size_t base = ((size_t)b * S_ + s0) * (size_t)D_ + d;

    // ---- Phase 1: local scan in registers (carry-independent) ----
    float A[R_], X[R_];
#pragma unroll
    for (int r = 0; r < R_; r++) A[r] = __ldcs(alpha + base + (size_t)r * D_);
#pragma unroll
    for (int r = 0; r < R_; r++) X[r] = __ldcs(x + base + (size_t)r * D_);

    float P = 1.0f, L = 0.0f;
#pragma unroll
    for (int r = 0; r < R_; r++) {
        L = fmaf(A[r], L, X[r]);   // local inclusive scan (zero seed)
        P = P * A[r];              // cumulative alpha product
        A[r] = P;                  // keep per-step cumprod
        X[r] = L;                  // keep per-step local scan
    }
    sp[w][lane] = P;
    sl[w][lane] = L;
    __syncthreads();

    // ---- Phase 2: inter-level chain (warp 0 only) ----
    if (w == 0) {
        float cin = 0.0f;
        if (level > 0) {
            if (lane == 0) {
                while (atomicAdd(&g_flags[level - 1][lg], 0) == 0) { /* spin */ }
            }
            __syncwarp();
            __threadfence();
            cin = __ldcg(&g_carry[level - 1][lg][lane]);
        }
        s_cin[lane] = cin;
        // block-inclusive carry-out for this level
        float h = cin;
#pragma unroll
        for (int w2 = 0; w2 < SUBS_; w2++)
            h = fmaf(sp[w2][lane], h, sl[w2][lane]);
        __stcg(&g_carry[level][lg][lane], h);
        __threadfence();
        __syncwarp();
        if (lane == 0) atomicExch(&g_flags[level][lg], 1);
    }
    __syncthreads();

    // ---- Phase 3: apply carry prefix, write output ----
    float h0 = s_cin[lane];
    for (int w2 = 0; w2 < w; w2++)
        h0 = fmaf(sp[w2][lane], h0, sl[w2][lane]);

#pragma unroll
    for (int r = 0; r < R_; r++)
        __stcs(out + base + (size_t)r * D_, fmaf(A[r], h0, X[r]));
}

extern "C" void kernel_launch(void* const* d_in, const int* in_sizes, int n_in,
                              void* d_out, int out_size) {
    const float* xp = (const float*)d_in[0];
    const float* ap = (const float*)d_in[1];
    float* op = (float*)d_out;

    // Reset chain flags (replay-safe), then the single-pass chained scan.
    zero_flags_kernel<<<(LEVELS_ * LG_ + 255) / 256, 256>>>();
    scan_kernel<<<dim3(LG_, LEVELS_), TPB_>>>(xp, ap, op);
}

// round 3
// speedup vs baseline: 1.2434x; 1.2434x over previous
#include <cuda_runtime.h>

// h_t = alpha_t * h_{t-1} + x_t over axis 1 of float32 [4, 8192, 1024].
// Single-pass scan with decoupled lookback over block aggregates:
// every block publishes its (prod alpha, local scan) aggregate right after
// Phase 1 (no dependencies), then folds its predecessors' aggregates itself.

#define B_      4
#define S_      8192
#define D_      1024
#define R_      16                    // s-steps per thread (register-resident)
#define SUBS_   16                    // s-subchunks (warps) per block
#define TPB_    512                   // 32 d-lanes x 16 subchunks
#define DTILE_  32                    // d-lanes per block (= warp width)
#define SCHUNK_ (R_ * SUBS_)          // 256 s-steps per block/level
#define LEVELS_ (S_ / SCHUNK_)        // 32 levels per lane chain
#define LG_     (B_ * (D_ / DTILE_))  // 128 independent lane-group chains

// Aggregate scratch (device globals: no allocation in kernel_launch).
// Layout keeps lane-contiguous 128B rows for coalesced lookback loads.
__device__ float g_aggP[LG_][LEVELS_][DTILE_];
__device__ float g_aggL[LG_][LEVELS_][DTILE_];
__device__ int   g_flags[LG_][LEVELS_];

__global__ void zero_flags_kernel() {
    int i = blockIdx.x * blockDim.x + threadIdx.x;
    if (i < LEVELS_ * LG_) ((int*)g_flags)[i] = 0;
}

__global__ __launch_bounds__(TPB_, 2) void scan_kernel(const float* __restrict__ x,
                                                       const float* __restrict__ alpha,
                                                       float* __restrict__ out) {
    __shared__ float sp[SUBS_][DTILE_];   // per-subchunk cumprod(alpha)
    __shared__ float sl[SUBS_][DTILE_];   // per-subchunk local scan value
    __shared__ float s_cin[DTILE_];       // carry-in for this block (per d-lane)

    const int tid   = threadIdx.x;
    const int lane  = tid & 31;           // d within tile
    const int w     = tid >> 5;           // s-subchunk index (0..15)
    const int lg    = blockIdx.x;         // lane-group: b * 32 + dtile
    const int level = blockIdx.y;         // s-chunk level
    const int b     = lg >> 5;
    const int dt    = lg & 31;
    const int d     = dt * DTILE_ + lane;
    const int s0    = level * SCHUNK_ + w * R_;
    const size_t base = ((size_t)b * S_ + s0) * (size_t)D_ + d;

    // ---- Phase 1: local scan in registers (carry-independent) ----
    float A[R_], X[R_];
#pragma unroll
    for (int r = 0; r < R_; r++) A[r] = __ldcs(alpha + base + (size_t)r * D_);
#pragma unroll
    for (int r = 0; r < R_; r++) X[r] = __ldcs(x + base + (size_t)r * D_);

    float P = 1.0f, L = 0.0f;
#pragma unroll
    for (int r = 0; r < R_; r++) {
        L = fmaf(A[r], L, X[r]);   // local inclusive scan (zero seed)
        P = P * A[r];              // cumulative alpha product
        A[r] = P;                  // keep per-step cumprod
        X[r] = L;                  // keep per-step local scan
    }
    sp[w][lane] = P;
    sl[w][lane] = L;
    __syncthreads();

    // ---- Phase 2 (warp 0): publish block aggregate, then lookback ----
    if (w == 0) {
        // Block aggregate across the 16 subchunks (per d-lane).
        float Pb = 1.0f, Lb = 0.0f;
#pragma unroll
        for (int w2 = 0; w2 < SUBS_; w2++) {
            Lb = fmaf(sp[w2][lane], Lb, sl[w2][lane]);
            Pb = Pb * sp[w2][lane];
        }
        // Publish immediately — successors only need aggregates.
        __stcg(&g_aggP[lg][level][lane], Pb);
        __stcg(&g_aggL[lg][level][lane], Lb);
        __threadfence();
        __syncwarp();
        if (lane == 0) atomicExch(&g_flags[lg][level], 1);

        // Lookback: fold aggregates of levels 0..level-1 (in order).
        float cin = 0.0f;
        if (level > 0) {
            volatile int* fl = &g_flags[lg][0];
            const bool need = (lane < level);
            while (__any_sync(0xffffffffu, need && (fl[lane] == 0))) { /* spin */ }
            __threadfence();
            int j = 0;
            while (j < level) {
                const int t = level - j;   // remaining
                float p0[4], l0[4];
#pragma unroll
                for (int k = 0; k < 4; k++) {
                    if (k < t) {
                        p0[k] = __ldcg(&g_aggP[lg][j + k][lane]);
                        l0[k] = __ldcg(&g_aggL[lg][j + k][lane]);
                    }
                }
#pragma unroll
                for (int k = 0; k < 4; k++)
                    if (k < t) cin = fmaf(p0[k], cin, l0[k]);
                j += 4;
            }
        }
        s_cin[lane] = cin;
    }
    __syncthreads();

    // ---- Phase 3: apply carry prefix, write output ----
    float h0 = s_cin[lane];
    for (int w2 = 0; w2 < w; w2++)
        h0 = fmaf(sp[w2][lane], h0, sl[w2][lane]);

#pragma unroll
    for (int r = 0; r < R_; r++)
        __stcs(out + base + (size_t)r * D_, fmaf(A[r], h0, X[r]));
}

extern "C" void kernel_launch(void* const* d_in, const int* in_sizes, int n_in,
                              void* d_out, int out_size) {
    const float* xp = (const float*)d_in[0];
    const float* ap = (const float*)d_in[1];
    float* op = (float*)d_out;

    zero_flags_kernel<<<(LEVELS_ * LG_ + 255) / 256, 256>>>();
    scan_kernel<<<dim3(LG_, LEVELS_), TPB_>>>(xp, ap, op);
}